// round 1
// baseline (speedup 1.0000x reference)
#include <cuda_runtime.h>

#define NTOK   4096
#define DMODEL 1024
#define NEXP   8
#define TOPK   2
#define HEXP   704
#define HSH    1408

#define BM 64
#define BN 64
#define BK 16
#define NTHREADS 256

// ---------------- scratch (device globals; no allocation allowed) ----------
__device__ int   g_cnt[NEXP];
__device__ int   g_off[NEXP + 1];
__device__ int   g_cur[NEXP];
__device__ int   g_topi[NTOK * TOPK];
__device__ float g_topw[NTOK * TOPK];
__device__ int   g_tok[NTOK * TOPK];
__device__ float g_gate[NTOK * TOPK];
__device__ float g_hid_r[NTOK * TOPK * HEXP];   // routed SwiGLU hidden (23 MB)
__device__ float g_hid_s[NTOK * HSH];           // shared-expert hidden (23 MB)

// ---------------- tiny setup kernels ---------------------------------------
__global__ void zero_kernel() {
    int t = threadIdx.x;
    if (t < NEXP) { g_cnt[t] = 0; g_cur[t] = 0; }
}

__global__ void scan_kernel() {
    int acc = 0;
    g_off[0] = 0;
    for (int e = 0; e < NEXP; e++) { acc += g_cnt[e]; g_off[e + 1] = acc; }
}

// one warp per token: logits -> softmax -> top2 -> normalized gates
__global__ void router_kernel(const float* __restrict__ x,
                              const float* __restrict__ Wg) {
    int gw   = (blockIdx.x * blockDim.x + threadIdx.x) >> 5;
    int lane = threadIdx.x & 31;
    if (gw >= NTOK) return;
    const float* xr = x + (size_t)gw * DMODEL;

    float acc[NEXP];
#pragma unroll
    for (int e = 0; e < NEXP; e++) acc[e] = 0.f;

    for (int k = lane; k < DMODEL; k += 32) {
        float xv = xr[k];
#pragma unroll
        for (int e = 0; e < NEXP; e++) acc[e] += xv * Wg[e * DMODEL + k];
    }
#pragma unroll
    for (int e = 0; e < NEXP; e++) {
#pragma unroll
        for (int o = 16; o > 0; o >>= 1)
            acc[e] += __shfl_xor_sync(0xffffffffu, acc[e], o);
    }
    if (lane == 0) {
        float m = acc[0];
#pragma unroll
        for (int e = 1; e < NEXP; e++) m = fmaxf(m, acc[e]);
        float p[NEXP], s = 0.f;
#pragma unroll
        for (int e = 0; e < NEXP; e++) { p[e] = expf(acc[e] - m); s += p[e]; }
        float inv = 1.f / s;
#pragma unroll
        for (int e = 0; e < NEXP; e++) p[e] *= inv;

        int   i0 = 0; float v0 = p[0];
#pragma unroll
        for (int e = 1; e < NEXP; e++) if (p[e] > v0) { v0 = p[e]; i0 = e; }
        int   i1 = (i0 == 0) ? 1 : 0; float v1 = p[i1];
#pragma unroll
        for (int e = 0; e < NEXP; e++)
            if (e != i0 && p[e] > v1) { v1 = p[e]; i1 = e; }

        float sw = v0 + v1 + 1e-20f;
        float w0 = v0 / sw, w1 = v1 / sw;
        g_topi[gw * 2]     = i0;  g_topi[gw * 2 + 1] = i1;
        g_topw[gw * 2]     = w0;  g_topw[gw * 2 + 1] = w1;
        atomicAdd(&g_cnt[i0], 1);
        atomicAdd(&g_cnt[i1], 1);
    }
}

__global__ void fill_kernel() {
    int n = blockIdx.x * blockDim.x + threadIdx.x;
    if (n >= NTOK) return;
#pragma unroll
    for (int s = 0; s < TOPK; s++) {
        int e   = g_topi[n * 2 + s];
        int pos = atomicAdd(&g_cur[e], 1);
        int idx = g_off[e] + pos;
        g_tok[idx]  = n;
        g_gate[idx] = g_topw[n * 2 + s];
    }
}

__device__ __forceinline__ float silu_f(float z) {
    return z / (1.f + __expf(-z));
}

// ---------------- GEMM1 routed: H = silu(Xg@W1e) * (Xg@W3e) ----------------
// grid: (HEXP/BN=11, NTOK/BM=64, NEXP), block 256
__global__ __launch_bounds__(NTHREADS)
void gemm1_routed(const float* __restrict__ x,
                  const float* __restrict__ W1,
                  const float* __restrict__ W3) {
    int e    = blockIdx.z;
    int base = g_off[e];
    int ne   = g_off[e + 1] - base;
    int m0   = blockIdx.y * BM;
    if (m0 >= ne) return;
    int n0 = blockIdx.x * BN;

    __shared__ float As[BK][BM + 4];
    __shared__ float Bs1[BK][BN];
    __shared__ float Bs3[BK][BN];
    __shared__ int   stok[BM];

    int tid = threadIdx.x;
    if (tid < BM) stok[tid] = (m0 + tid < ne) ? g_tok[base + m0 + tid] : -1;
    __syncthreads();

    const float* B1 = W1 + (size_t)e * DMODEL * HEXP + n0;
    const float* B3 = W3 + (size_t)e * DMODEL * HEXP + n0;

    int ar = tid >> 2, ac = (tid & 3) * 4;
    int br = tid >> 4, bc = (tid & 15) * 4;
    int atok = stok[ar];
    const float* Aptr = (atok >= 0) ? (x + (size_t)atok * DMODEL + ac) : 0;

    float4 av = make_float4(0.f, 0.f, 0.f, 0.f);
    if (Aptr) av = *(const float4*)Aptr;
    float4 b1v = *(const float4*)(B1 + (size_t)br * HEXP + bc);
    float4 b3v = *(const float4*)(B3 + (size_t)br * HEXP + bc);

    int tm0 = (tid >> 4) * 4, tn0 = (tid & 15) * 4;
    float acc1[4][4] = {}, acc3[4][4] = {};

    for (int kk = 0; kk < DMODEL; kk += BK) {
        As[ac + 0][ar] = av.x; As[ac + 1][ar] = av.y;
        As[ac + 2][ar] = av.z; As[ac + 3][ar] = av.w;
        *(float4*)&Bs1[br][bc] = b1v;
        *(float4*)&Bs3[br][bc] = b3v;
        __syncthreads();
        int kn = kk + BK;
        if (kn < DMODEL) {
            if (Aptr) av = *(const float4*)(Aptr + kn);
            b1v = *(const float4*)(B1 + (size_t)(kn + br) * HEXP + bc);
            b3v = *(const float4*)(B3 + (size_t)(kn + br) * HEXP + bc);
        }
#pragma unroll
        for (int k = 0; k < BK; k++) {
            float4 a  = *(const float4*)&As[k][tm0];
            float4 b1 = *(const float4*)&Bs1[k][tn0];
            float4 b3 = *(const float4*)&Bs3[k][tn0];
            float aa[4]  = { a.x, a.y, a.z, a.w };
            float bb1[4] = { b1.x, b1.y, b1.z, b1.w };
            float bb3[4] = { b3.x, b3.y, b3.z, b3.w };
#pragma unroll
            for (int i = 0; i < 4; i++)
#pragma unroll
                for (int j = 0; j < 4; j++) {
                    acc1[i][j] = fmaf(aa[i], bb1[j], acc1[i][j]);
                    acc3[i][j] = fmaf(aa[i], bb3[j], acc3[i][j]);
                }
        }
        __syncthreads();
    }
#pragma unroll
    for (int i = 0; i < 4; i++) {
        int r = tm0 + i;
        if (m0 + r < ne) {
            float4 hv;
            hv.x = silu_f(acc1[i][0]) * acc3[i][0];
            hv.y = silu_f(acc1[i][1]) * acc3[i][1];
            hv.z = silu_f(acc1[i][2]) * acc3[i][2];
            hv.w = silu_f(acc1[i][3]) * acc3[i][3];
            *(float4*)&g_hid_r[(size_t)(base + m0 + r) * HEXP + n0 + tn0] = hv;
        }
    }
}

// ---------------- GEMM2 routed: out += gate * (H @ W2e), scatter -----------
// grid: (DMODEL/BN=16, NTOK/BM=64, NEXP)
__global__ __launch_bounds__(NTHREADS)
void gemm2_routed(const float* __restrict__ W2, float* __restrict__ out) {
    int e    = blockIdx.z;
    int base = g_off[e];
    int ne   = g_off[e + 1] - base;
    int m0   = blockIdx.y * BM;
    if (m0 >= ne) return;
    int n0 = blockIdx.x * BN;

    __shared__ float As[BK][BM + 4];
    __shared__ float Bs[BK][BN];
    __shared__ int   stok[BM];
    __shared__ float sgate[BM];

    int tid = threadIdx.x;
    if (tid < BM) {
        bool v = (m0 + tid < ne);
        stok[tid]  = v ? g_tok[base + m0 + tid] : -1;
        sgate[tid] = v ? g_gate[base + m0 + tid] : 0.f;
    }
    __syncthreads();

    const float* Bp = W2 + (size_t)e * HEXP * DMODEL + n0;

    int ar = tid >> 2, ac = (tid & 3) * 4;
    int br = tid >> 4, bc = (tid & 15) * 4;
    bool arow_ok = (m0 + ar < ne);
    const float* Aptr = g_hid_r + (size_t)(base + m0 + ar) * HEXP + ac;

    float4 av = make_float4(0.f, 0.f, 0.f, 0.f);
    if (arow_ok) av = *(const float4*)Aptr;
    float4 bv = *(const float4*)(Bp + (size_t)br * DMODEL + bc);

    int tm0 = (tid >> 4) * 4, tn0 = (tid & 15) * 4;
    float acc[4][4] = {};

    for (int kk = 0; kk < HEXP; kk += BK) {
        As[ac + 0][ar] = av.x; As[ac + 1][ar] = av.y;
        As[ac + 2][ar] = av.z; As[ac + 3][ar] = av.w;
        *(float4*)&Bs[br][bc] = bv;
        __syncthreads();
        int kn = kk + BK;
        if (kn < HEXP) {
            if (arow_ok) av = *(const float4*)(Aptr + kn);
            bv = *(const float4*)(Bp + (size_t)(kn + br) * DMODEL + bc);
        }
#pragma unroll
        for (int k = 0; k < BK; k++) {
            float4 a = *(const float4*)&As[k][tm0];
            float4 b = *(const float4*)&Bs[k][tn0];
            float aa[4] = { a.x, a.y, a.z, a.w };
            float bb[4] = { b.x, b.y, b.z, b.w };
#pragma unroll
            for (int i = 0; i < 4; i++)
#pragma unroll
                for (int j = 0; j < 4; j++)
                    acc[i][j] = fmaf(aa[i], bb[j], acc[i][j]);
        }
        __syncthreads();
    }
#pragma unroll
    for (int i = 0; i < 4; i++) {
        int r = tm0 + i;
        if (m0 + r < ne) {
            int   tk = stok[r];
            float w  = sgate[r];
            float* op = out + (size_t)tk * DMODEL + n0 + tn0;
#pragma unroll
            for (int j = 0; j < 4; j++)
                atomicAdd(op + j, w * acc[i][j]);
        }
    }
}

// ---------------- GEMM1 shared expert: Hs = silu(X@Ws1)*(X@Ws3) ------------
// grid: (HSH/BN=22, NTOK/BM=64)
__global__ __launch_bounds__(NTHREADS)
void gemm1_shared(const float* __restrict__ x,
                  const float* __restrict__ Ws1,
                  const float* __restrict__ Ws3) {
    int m0 = blockIdx.y * BM;
    int n0 = blockIdx.x * BN;

    __shared__ float As[BK][BM + 4];
    __shared__ float Bs1[BK][BN];
    __shared__ float Bs3[BK][BN];

    int tid = threadIdx.x;
    const float* B1 = Ws1 + n0;
    const float* B3 = Ws3 + n0;

    int ar = tid >> 2, ac = (tid & 3) * 4;
    int br = tid >> 4, bc = (tid & 15) * 4;
    const float* Aptr = x + (size_t)(m0 + ar) * DMODEL + ac;

    float4 av  = *(const float4*)Aptr;
    float4 b1v = *(const float4*)(B1 + (size_t)br * HSH + bc);
    float4 b3v = *(const float4*)(B3 + (size_t)br * HSH + bc);

    int tm0 = (tid >> 4) * 4, tn0 = (tid & 15) * 4;
    float acc1[4][4] = {}, acc3[4][4] = {};

    for (int kk = 0; kk < DMODEL; kk += BK) {
        As[ac + 0][ar] = av.x; As[ac + 1][ar] = av.y;
        As[ac + 2][ar] = av.z; As[ac + 3][ar] = av.w;
        *(float4*)&Bs1[br][bc] = b1v;
        *(float4*)&Bs3[br][bc] = b3v;
        __syncthreads();
        int kn = kk + BK;
        if (kn < DMODEL) {
            av  = *(const float4*)(Aptr + kn);
            b1v = *(const float4*)(B1 + (size_t)(kn + br) * HSH + bc);
            b3v = *(const float4*)(B3 + (size_t)(kn + br) * HSH + bc);
        }
#pragma unroll
        for (int k = 0; k < BK; k++) {
            float4 a  = *(const float4*)&As[k][tm0];
            float4 b1 = *(const float4*)&Bs1[k][tn0];
            float4 b3 = *(const float4*)&Bs3[k][tn0];
            float aa[4]  = { a.x, a.y, a.z, a.w };
            float bb1[4] = { b1.x, b1.y, b1.z, b1.w };
            float bb3[4] = { b3.x, b3.y, b3.z, b3.w };
#pragma unroll
            for (int i = 0; i < 4; i++)
#pragma unroll
                for (int j = 0; j < 4; j++) {
                    acc1[i][j] = fmaf(aa[i], bb1[j], acc1[i][j]);
                    acc3[i][j] = fmaf(aa[i], bb3[j], acc3[i][j]);
                }
        }
        __syncthreads();
    }
#pragma unroll
    for (int i = 0; i < 4; i++) {
        int r = tm0 + i;
        float4 hv;
        hv.x = silu_f(acc1[i][0]) * acc3[i][0];
        hv.y = silu_f(acc1[i][1]) * acc3[i][1];
        hv.z = silu_f(acc1[i][2]) * acc3[i][2];
        hv.w = silu_f(acc1[i][3]) * acc3[i][3];
        *(float4*)&g_hid_s[(size_t)(m0 + r) * HSH + n0 + tn0] = hv;
    }
}

// ---------------- GEMM2 shared expert: out = Hs @ Ws2 (plain write) --------
// grid: (DMODEL/BN=16, NTOK/BM=64)
__global__ __launch_bounds__(NTHREADS)
void gemm2_shared(const float* __restrict__ Ws2, float* __restrict__ out) {
    int m0 = blockIdx.y * BM;
    int n0 = blockIdx.x * BN;

    __shared__ float As[BK][BM + 4];
    __shared__ float Bs[BK][BN];

    int tid = threadIdx.x;
    const float* Bp = Ws2 + n0;

    int ar = tid >> 2, ac = (tid & 3) * 4;
    int br = tid >> 4, bc = (tid & 15) * 4;
    const float* Aptr = g_hid_s + (size_t)(m0 + ar) * HSH + ac;

    float4 av = *(const float4*)Aptr;
    float4 bv = *(const float4*)(Bp + (size_t)br * DMODEL + bc);

    int tm0 = (tid >> 4) * 4, tn0 = (tid & 15) * 4;
    float acc[4][4] = {};

    for (int kk = 0; kk < HSH; kk += BK) {
        As[ac + 0][ar] = av.x; As[ac + 1][ar] = av.y;
        As[ac + 2][ar] = av.z; As[ac + 3][ar] = av.w;
        *(float4*)&Bs[br][bc] = bv;
        __syncthreads();
        int kn = kk + BK;
        if (kn < HSH) {
            av = *(const float4*)(Aptr + kn);
            bv = *(const float4*)(Bp + (size_t)(kn + br) * DMODEL + bc);
        }
#pragma unroll
        for (int k = 0; k < BK; k++) {
            float4 a = *(const float4*)&As[k][tm0];
            float4 b = *(const float4*)&Bs[k][tn0];
            float aa[4] = { a.x, a.y, a.z, a.w };
            float bb[4] = { b.x, b.y, b.z, b.w };
#pragma unroll
            for (int i = 0; i < 4; i++)
#pragma unroll
                for (int j = 0; j < 4; j++)
                    acc[i][j] = fmaf(aa[i], bb[j], acc[i][j]);
        }
        __syncthreads();
    }
#pragma unroll
    for (int i = 0; i < 4; i++) {
        int r = tm0 + i;
        float4 ov = make_float4(acc[i][0], acc[i][1], acc[i][2], acc[i][3]);
        *(float4*)&out[(size_t)(m0 + r) * DMODEL + n0 + tn0] = ov;
    }
}

// ---------------- launch ----------------------------------------------------
extern "C" void kernel_launch(void* const* d_in, const int* in_sizes, int n_in,
                              void* d_out, int out_size) {
    const float* x   = (const float*)d_in[0];
    const float* Wg  = (const float*)d_in[1];
    const float* W1  = (const float*)d_in[2];
    const float* W3  = (const float*)d_in[3];
    const float* W2  = (const float*)d_in[4];
    const float* Ws1 = (const float*)d_in[5];
    const float* Ws3 = (const float*)d_in[6];
    const float* Ws2 = (const float*)d_in[7];
    float* out = (float*)d_out;

    zero_kernel<<<1, 32>>>();
    router_kernel<<<NTOK / 8, 256>>>(x, Wg);   // 8 warps/block, 1 token/warp
    scan_kernel<<<1, 1>>>();
    fill_kernel<<<NTOK / 256, 256>>>();

    // shared expert (writes every element of out) must precede routed scatter
    gemm1_shared<<<dim3(HSH / BN, NTOK / BM), NTHREADS>>>(x, Ws1, Ws3);
    gemm2_shared<<<dim3(DMODEL / BN, NTOK / BM), NTHREADS>>>(Ws2, out);

    gemm1_routed<<<dim3(HEXP / BN, NTOK / BM, NEXP), NTHREADS>>>(x, W1, W3);
    gemm2_routed<<<dim3(DMODEL / BN, NTOK / BM, NEXP), NTHREADS>>>(W2, out);
}